// round 12
// baseline (speedup 1.0000x reference)
#include <cuda_runtime.h>

#define GRIDA 444
#define GRIDB 888
#define TPB   256
#define MAXB  1048576

__constant__ float cW1[30];                 // W1 via one direct D2D memcpy node

__device__ float4 g_hn[MAXB];               // z = (h-mu)*rsqrt(var+eps), pre-affine (A -> B)
__device__ float  g_partials[GRIDA * 16];   // per-block [8 sums, 8 sumsq]
// g_final: [0:6) m', [6:12) c2', [12:36) w2p (W2 pre-scaled by sc), [36:39) bp
__device__ float  g_final[39];
__device__ unsigned g_done = 0;             // self-resetting ticket (replay-safe)

__device__ __forceinline__ float ex2f(float x) {
    float y; asm("ex2.approx.ftz.f32 %0, %1;" : "=f"(y) : "f"(x)); return y;
}
__device__ __forceinline__ float sin_fast(float x) {
    float y; asm("sin.approx.ftz.f32 %0, %1;" : "=f"(y) : "f"(x)); return y;
}

// =======================  PASS A  =======================
// Coalesced smem staging (10 L1 wavefronts/warp-tile) + cbank W1 (no GPR/LDS cost).
__global__ __launch_bounds__(TPB, 3)
void passA(const float* __restrict__ xg,
           const float* __restrict__ b1,
           const float* __restrict__ gam, const float* __restrict__ bet,
           const float* __restrict__ mIn, const float* __restrict__ th,
           const float* __restrict__ g2, const float* __restrict__ bt2,
           const float* __restrict__ W2, const float* __restrict__ b2,
           int n)
{
    __shared__ float sprm[21];         // b1 0..2, gam 3..5, bet 6..8, m 9..14, th 15..20
    __shared__ float stage[8 * 352];   // 8 warps x 32 rows x 11 floats (pad 11 -> conflict-free)
    __shared__ float red[128];
    __shared__ float red2[256];
    __shared__ float tot[24];
    __shared__ float t2s[8];
    __shared__ int   sflag;

    const int tid = threadIdx.x, bid = blockIdx.x;
    const int wid = tid >> 5, lane = tid & 31;

    if      (tid < 3)  sprm[tid] = b1[tid];
    else if (tid < 6)  sprm[tid] = gam[tid - 3];
    else if (tid < 9)  sprm[tid] = bet[tid - 6];
    else if (tid < 15) sprm[tid] = mIn[tid - 9];
    else if (tid < 21) sprm[tid] = th[tid - 15];
    __syncthreads();

    // fold LN affine into membership constants:
    //   m'[k] = (m[k] - bet[q]) / gam[q],  c2'[k] = -log2e/(2 th^2) * gam[q]^2
    float bb1[3], mv[6], c2[6];
#pragma unroll
    for (int i = 0; i < 3; i++) bb1[i] = sprm[i];
#pragma unroll
    for (int k = 0; k < 6; k++) {
        const int q = k >> 1;
        const float g = sprm[3 + q], b = sprm[6 + q];
        const float t = sprm[15 + k];
        mv[k] = (sprm[9 + k] - b) / g;
        c2[k] = (-1.4426950408889634f / (2.0f * t * t)) * g * g;
    }

    // hoisted staging offsets: dest_off[j] for idx = j*32+lane -> (idx/10)*11 + idx%10
    int dest_off[10];
#pragma unroll
    for (int j = 0; j < 10; j++) {
        const int idx = j * 32 + lane;
        dest_off[j] = (idx / 10) * 11 + (idx % 10);
    }

    float* buf = stage + wid * 352;
    const float C2 = 0.99999f * 0.99999f;
    const int NTOT = GRIDA * TPB;

    float acc[16];
#pragma unroll
    for (int i = 0; i < 16; i++) acc[i] = 0.f;

    for (int warpBase = bid * TPB + wid * 32; warpBase < n; warpBase += NTOT) {
        // coalesced stage: 320 consecutive floats per warp
        const float* src = xg + (size_t)warpBase * 10;
        const int lim = min(320, (n - warpBase) * 10);
#pragma unroll
        for (int j = 0; j < 10; j++) {
            const int idx = j * 32 + lane;
            if (idx < lim) buf[dest_off[j]] = src[idx];
        }
        __syncwarp();
        const int r = warpBase + lane;
        if (r < n) {
            float xv[10];
#pragma unroll
            for (int j = 0; j < 10; j++) xv[j] = buf[lane * 11 + j];

            float h[3];
#pragma unroll
            for (int q = 0; q < 3; q++) {
                float a = bb1[q];
#pragma unroll
                for (int c = 0; c < 10; c++) a = fmaf(xv[c], cW1[q * 10 + c], a);
                h[q] = a;
            }
            const float mu = (h[0] + h[1] + h[2]) * (1.0f / 3.0f);
            const float d0 = h[0] - mu, d1 = h[1] - mu, d2 = h[2] - mu;
            const float var = (d0 * d0 + d1 * d1 + d2 * d2) * (1.0f / 3.0f);
            const float rn = rsqrtf(var + 1e-5f);
            const float z0 = d0 * rn, z1 = d1 * rn, z2 = d2 * rn;
            g_hn[r] = make_float4(z0, z1, z2, 0.f);

            float p[6];
#pragma unroll
            for (int kk = 0; kk < 6; kk++) {
                const float zq = (kk < 2) ? z0 : (kk < 4) ? z1 : z2;
                const float a = zq - mv[kk];
                const float f = ex2f(a * a * c2[kk]);
                const float pv = fminf(f + 1e-16f, C2);
                p[kk] = (kk < 2) ? pv : (1.0f - pv);
            }
            const float w00 = p[2] * p[4], w01 = p[2] * p[5];
            const float w10 = p[3] * p[4], w11 = p[3] * p[5];
            float o[8];
            o[0] = p[0] * w00; o[1] = p[0] * w01; o[2] = p[0] * w10; o[3] = p[0] * w11;
            o[4] = p[1] * w00; o[5] = p[1] * w01; o[6] = p[1] * w10; o[7] = p[1] * w11;
#pragma unroll
            for (int c = 0; c < 8; c++) {
                acc[c] += o[c];
                acc[8 + c] = fmaf(o[c], o[c], acc[8 + c]);
            }
        }
        __syncwarp();
    }

    // deterministic block reduction -> g_partials
    __syncthreads();
#pragma unroll
    for (int kk = 0; kk < 16; kk++) {
        float v = acc[kk];
#pragma unroll
        for (int off = 16; off; off >>= 1)
            v += __shfl_down_sync(0xffffffffu, v, off);
        if (lane == 0) red[wid * 16 + kk] = v;
    }
    __syncthreads();
    if (tid < 16) {
        float s = 0.f;
#pragma unroll
        for (int w = 0; w < 8; w++) s += red[w * 16 + tid];
        g_partials[bid * 16 + tid] = s;
    }

    // ---- last block folds partials -> full passB param block in g_final ----
    if (tid == 0) {
        __threadfence();
        const unsigned t = atomicAdd(&g_done, 1u);
        sflag = (t == GRIDA - 1u) ? 1 : 0;
    }
    __syncthreads();
    if (sflag) {
        {
            const int met = tid & 15, ch = tid >> 4;
            float s = 0.f;
            for (int b = ch; b < GRIDA; b += 16)
                s += __ldcg(&g_partials[b * 16 + met]);
            red2[tid] = s;
        }
        __syncthreads();
        if (tid < 16) {
            float s = 0.f;
#pragma unroll
            for (int w = 0; w < 16; w++) s += red2[w * 16 + tid];
            tot[tid] = s;            // [0:8) sums, [8:16) sumsq
        }
        __syncthreads();
        if (tid < 8) {
            const float invB = 1.0f / (float)n;
            const float muv = tot[tid] * invB;
            const float msq = tot[8 + tid] * invB;
            const float var = msq - muv * muv;
            const float sc = g2[tid] * rsqrtf(var + 1e-5f);
            tot[16 + tid] = sc;
            t2s[tid] = bt2[tid] - muv * sc;
        }
        __syncthreads();
        if (tid < 6)       g_final[tid] = mv[tid];        // transformed m'
        else if (tid < 12) g_final[tid] = c2[tid - 6];    // transformed c2'
        else if (tid < 36) {            // w2p[i*8+c] = W2[i*8+c] * sc[c]
            const int i = (tid - 12) >> 3, c = (tid - 12) & 7;
            g_final[tid] = W2[i * 8 + c] * tot[16 + c];
        } else if (tid < 39) {          // bp[i] = b2[i] + sum_c t2[c]*W2[i*8+c]
            const int i = tid - 36;
            float a = b2[i];
#pragma unroll
            for (int c = 0; c < 8; c++) a = fmaf(t2s[c], W2[i * 8 + c], a);
            g_final[tid] = a;
        }
        if (tid == 0) g_done = 0;    // reset for next replay
    }
}

// =======================  PASS B  (unchanged from R11, measured 10.4us)  =======================
__global__ __launch_bounds__(TPB, 3)
void passB(float* __restrict__ outg, int n)
{
    __shared__ float sf[40];
    const int tid = threadIdx.x, bid = blockIdx.x;

    if (tid < 39) sf[tid] = g_final[tid];
    __syncthreads();

    float mv[6], c2[6], w2p[24], bp[3];
#pragma unroll
    for (int i = 0; i < 6; i++) { mv[i] = sf[i]; c2[i] = sf[6 + i]; }
#pragma unroll
    for (int i = 0; i < 24; i++) w2p[i] = sf[12 + i];
#pragma unroll
    for (int i = 0; i < 3; i++) bp[i] = sf[36 + i];

    const float C2 = 0.99999f * 0.99999f;
    const int NTB = GRIDB * TPB;

    for (int base = bid * TPB + tid; base < n; base += 2 * NTB) {
        const int r0 = base, r1 = base + NTB;
        const float4 hv0 = g_hn[r0];
        float4 hv1;
        const bool v1 = r1 < n;
        if (v1) hv1 = g_hn[r1];

#pragma unroll
        for (int rr = 0; rr < 2; rr++) {
            if (rr == 1 && !v1) break;
            const float4 hv = (rr == 0) ? hv0 : hv1;
            const int r = (rr == 0) ? r0 : r1;
            float p[6];
#pragma unroll
            for (int kk = 0; kk < 6; kk++) {
                const float zq = (kk < 2) ? hv.x : (kk < 4) ? hv.y : hv.z;
                const float a = zq - mv[kk];
                const float f = ex2f(a * a * c2[kk]);
                const float pv = fminf(f + 1e-16f, C2);
                p[kk] = (kk < 2) ? pv : (1.0f - pv);
            }
            const float w00 = p[2] * p[4], w01 = p[2] * p[5];
            const float w10 = p[3] * p[4], w11 = p[3] * p[5];
            float o[8];
            o[0] = p[0] * w00; o[1] = p[0] * w01; o[2] = p[0] * w10; o[3] = p[0] * w11;
            o[4] = p[1] * w00; o[5] = p[1] * w01; o[6] = p[1] * w10; o[7] = p[1] * w11;
            float lg[3];
#pragma unroll
            for (int i = 0; i < 3; i++) {
                float a = bp[i];
#pragma unroll
                for (int c = 0; c < 8; c++) a = fmaf(o[c], w2p[i * 8 + c], a);
                lg[i] = a;
            }
            const float sg0 = sin_fast(lg[0] * 0.5f);
            const float sg1 = sin_fast(lg[1] * 0.5f);
            const float sg2 = sin_fast(lg[2] * 0.5f);
            const float pq0 = sg0 * sg0, pq1 = sg1 * sg1, pq2 = sg2 * sg2;
            const float cq0 = 1.f - pq0, cq1 = 1.f - pq1, cq2 = 1.f - pq2;
            const float tt = cq1 * cq2;
            float* dst = outg + (size_t)r * 3;
            dst[0] = cq0 * tt;
            dst[1] = pq0 * tt;
            dst[2] = cq0 * (pq1 * cq2);
        }
    }
}

extern "C" void kernel_launch(void* const* d_in, const int* in_sizes, int n_in,
                              void* d_out, int out_size)
{
    const float* x = (const float*)d_in[0];
    const int n = in_sizes[0] / 10;

    // single memcpy node: W1 -> cbank
    cudaMemcpyToSymbolAsync(cW1, d_in[1], 30 * sizeof(float), 0,
                            cudaMemcpyDeviceToDevice, 0);

    passA<<<GRIDA, TPB>>>(x,
        (const float*)d_in[2], (const float*)d_in[3], (const float*)d_in[4],
        (const float*)d_in[5], (const float*)d_in[6], (const float*)d_in[7],
        (const float*)d_in[8], (const float*)d_in[9], (const float*)d_in[10], n);

    passB<<<GRIDB, TPB>>>((float*)d_out, n);
}

// round 13
// speedup vs baseline: 1.1622x; 1.1622x over previous
#include <cuda_runtime.h>

#define GRID 148
#define TPB  1024

__constant__ float cW1[30];   // W1[q][k], direct memcpy node
__constant__ float cW2[80];   // W2[i][c], direct memcpy node

__device__ unsigned g_counter = 0;          // monotone ticket counter (replay-safe)
__device__ float g_partials[GRID * 16];     // [block][8 sums, 8 sumsq]

__device__ __forceinline__ float ex2f(float x) {
    float y; asm("ex2.approx.ftz.f32 %0, %1;" : "=f"(y) : "f"(x)); return y;
}
__device__ __forceinline__ float sin_fast(float x) {
    float y; asm("sin.approx.ftz.f32 %0, %1;" : "=f"(y) : "f"(x)); return y;
}

__global__ __launch_bounds__(TPB, 1)
void qfnn_kernel(const float* __restrict__ xg, float* __restrict__ outg,
                 const float* __restrict__ b1g, const float* __restrict__ gamg,
                 const float* __restrict__ betg, const float* __restrict__ mg,
                 const float* __restrict__ thg, const float* __restrict__ g2g,
                 const float* __restrict__ bt2g, const float* __restrict__ b2g,
                 int n, int rpb)
{
    extern __shared__ float sm[];
    float* ps  = sm;                 // 6*rpb : cached memberships (6 planes)
    float* red = sm + 6 * rpb;       // 512 reduction scratch
    float* s2s = red + 512;          // 8 : sc
    float* t2s = s2s + 8;            // 8 : t2
    float* b2p = t2s + 8;            // 4 : folded bias
    float* sprm = b2p + 4;           // 21 : small-param staging

    const int bid = blockIdx.x, tid = threadIdx.x;

    // ---- prologue: small params -> smem -> registers ----
    if      (tid < 3)  sprm[tid] = b1g[tid];
    else if (tid < 6)  sprm[tid] = gamg[tid - 3];
    else if (tid < 9)  sprm[tid] = betg[tid - 6];
    else if (tid < 15) sprm[tid] = mg[tid - 9];
    else if (tid < 21) sprm[tid] = thg[tid - 15];
    __syncthreads();

    // fold LN affine: m'[k] = (m[k]-bet[q])/gam[q], c2'[k] = -log2e/(2 th^2) * gam[q]^2
    float bb1[3], mv[6], c2[6];
#pragma unroll
    for (int i = 0; i < 3; i++) bb1[i] = sprm[i];
#pragma unroll
    for (int k = 0; k < 6; k++) {
        const int q = k >> 1;
        const float g = sprm[3 + q], b = sprm[6 + q], t = sprm[15 + k];
        mv[k] = (sprm[9 + k] - b) / g;
        c2[k] = (-1.4426950408889634f / (2.0f * t * t)) * g * g;
    }

    const int row0 = bid * rpb;
    int nrows = n - row0;
    if (nrows > rpb) nrows = rpb;
    if (nrows < 0) nrows = 0;

    float accS[8], accQ[8];
#pragma unroll
    for (int c = 0; c < 8; c++) { accS[c] = 0.f; accQ[c] = 0.f; }

    const float C2 = 0.99999f * 0.99999f;
    const int ntiles = (nrows + TPB - 1) / TPB;

    // ---------------- Pass 1 (barrier-free): x -> memberships + channel sums ----------------
    for (int t = 0; t < ntiles; t++) {
        const int r = t * TPB + tid;
        if (r < nrows) {
            const float2* xp = (const float2*)(xg + (size_t)(row0 + r) * 10);
            const float2 v0 = xp[0], v1 = xp[1], v2 = xp[2], v3 = xp[3], v4 = xp[4];
            const float xv[10] = {v0.x, v0.y, v1.x, v1.y, v2.x,
                                  v2.y, v3.x, v3.y, v4.x, v4.y};
            float h[3];
#pragma unroll
            for (int q = 0; q < 3; q++) {
                float a = bb1[q];
#pragma unroll
                for (int k = 0; k < 10; k++) a = fmaf(xv[k], cW1[q * 10 + k], a);
                h[q] = a;
            }
            const float mu = (h[0] + h[1] + h[2]) * (1.0f / 3.0f);
            const float d0 = h[0] - mu, d1 = h[1] - mu, d2 = h[2] - mu;
            const float var = (d0 * d0 + d1 * d1 + d2 * d2) * (1.0f / 3.0f);
            const float rn = rsqrtf(var + 1e-5f);
            const float z0 = d0 * rn, z1 = d1 * rn, z2 = d2 * rn;  // pre-affine LN

            float p[6];
#pragma unroll
            for (int kk = 0; kk < 6; kk++) {
                const float zq = (kk < 2) ? z0 : (kk < 4) ? z1 : z2;
                const float a = zq - mv[kk];
                const float f = ex2f(a * a * c2[kk]);
                const float pv = fminf(f + 1e-16f, C2);
                p[kk] = (kk < 2) ? pv : (1.0f - pv);
            }
            ps[0 * rpb + r] = p[0]; ps[1 * rpb + r] = p[1];
            ps[2 * rpb + r] = p[2]; ps[3 * rpb + r] = p[3];
            ps[4 * rpb + r] = p[4]; ps[5 * rpb + r] = p[5];

            const float w00 = p[2] * p[4], w01 = p[2] * p[5];
            const float w10 = p[3] * p[4], w11 = p[3] * p[5];
            float o[8];
            o[0] = p[0] * w00; o[1] = p[0] * w01; o[2] = p[0] * w10; o[3] = p[0] * w11;
            o[4] = p[1] * w00; o[5] = p[1] * w01; o[6] = p[1] * w10; o[7] = p[1] * w11;
#pragma unroll
            for (int c = 0; c < 8; c++) {
                accS[c] += o[c];
                accQ[c] = fmaf(o[c], o[c], accQ[c]);
            }
        }
    }

    // ---------------- Block reduction (deterministic) ----------------
    {
        const int lane = tid & 31, wrp = tid >> 5;
#pragma unroll
        for (int k = 0; k < 16; k++) {
            float v = (k < 8) ? accS[k] : accQ[k - 8];
#pragma unroll
            for (int off = 16; off; off >>= 1)
                v += __shfl_down_sync(0xffffffffu, v, off);
            if (lane == 0) red[wrp * 16 + k] = v;
        }
    }
    __syncthreads();
    if (tid < 16) {
        float s = 0.f;
#pragma unroll
        for (int w = 0; w < TPB / 32; w++) s += red[w * 16 + tid];
        g_partials[bid * 16 + tid] = s;
        __threadfence();
    }
    __syncthreads();

    // ---------------- Grid barrier (ticketed, replay-safe) ----------------
    if (tid == 0) {
        __threadfence();
        const unsigned tk = atomicAdd(&g_counter, 1u);
        const unsigned target = (tk / GRID + 1u) * GRID;
        while (*((volatile unsigned*)&g_counter) < target) { }
    }
    __syncthreads();
    __threadfence();

    // ---------------- Finalize BN constants ----------------
    if (tid < 16) {
        float s0 = 0.f, s1 = 0.f, s2v = 0.f, s3 = 0.f;
#pragma unroll 4
        for (int b = 0; b < GRID; b += 4) {
            s0  += __ldcg(&g_partials[(b + 0) * 16 + tid]);
            s1  += __ldcg(&g_partials[(b + 1) * 16 + tid]);
            s2v += __ldcg(&g_partials[(b + 2) * 16 + tid]);
            s3  += __ldcg(&g_partials[(b + 3) * 16 + tid]);
        }
        red[tid] = (s0 + s1) + (s2v + s3);
    }
    __syncthreads();
    if (tid < 8) {
        const float invB = 1.0f / (float)n;
        const float muv = red[tid] * invB;
        const float msq = red[tid + 8] * invB;
        const float var = msq - muv * muv;
        const float sc = g2g[tid] * rsqrtf(var + 1e-5f);
        s2s[tid] = sc;
        t2s[tid] = bt2g[tid] - muv * sc;
    }
    __syncthreads();
    if (tid < 3) {
        float a = b2g[tid];
#pragma unroll
        for (int c = 0; c < 8; c++) a = fmaf(t2s[c], cW2[tid * 8 + c], a);
        b2p[tid] = a;
    }
    __syncthreads();
    float scr[8], bp[3];
#pragma unroll
    for (int c = 0; c < 8; c++) scr[c] = s2s[c];
#pragma unroll
    for (int i = 0; i < 3; i++) bp[i] = b2p[i];

    // ---------------- Pass 2 (barrier-free): memberships -> BN -> logits -> result ----------------
    for (int t = 0; t < ntiles; t++) {
        const int r = t * TPB + tid;
        if (r < nrows) {
            const float p0 = ps[0 * rpb + r], p1 = ps[1 * rpb + r];
            const float p2 = ps[2 * rpb + r], p3 = ps[3 * rpb + r];
            const float p4 = ps[4 * rpb + r], p5 = ps[5 * rpb + r];
            const float w00 = p2 * p4, w01 = p2 * p5, w10 = p3 * p4, w11 = p3 * p5;
            float u[8];
            u[0] = p0 * w00 * scr[0]; u[1] = p0 * w01 * scr[1];
            u[2] = p0 * w10 * scr[2]; u[3] = p0 * w11 * scr[3];
            u[4] = p1 * w00 * scr[4]; u[5] = p1 * w01 * scr[5];
            u[6] = p1 * w10 * scr[6]; u[7] = p1 * w11 * scr[7];
            float lg[3];
#pragma unroll
            for (int i = 0; i < 3; i++) {
                float a = bp[i];
#pragma unroll
                for (int c = 0; c < 8; c++) a = fmaf(u[c], cW2[i * 8 + c], a);
                lg[i] = a;
            }
            const float sg0 = sin_fast(lg[0] * 0.5f);
            const float sg1 = sin_fast(lg[1] * 0.5f);
            const float sg2 = sin_fast(lg[2] * 0.5f);
            const float pq0 = sg0 * sg0, pq1 = sg1 * sg1, pq2 = sg2 * sg2;
            const float cq0 = 1.f - pq0, cq1 = 1.f - pq1, cq2 = 1.f - pq2;
            const float tt = cq1 * cq2;
            float* dst = outg + (size_t)(row0 + r) * 3;
            dst[0] = cq0 * tt;
            dst[1] = pq0 * tt;
            dst[2] = cq0 * (pq1 * cq2);
        }
    }
}

extern "C" void kernel_launch(void* const* d_in, const int* in_sizes, int n_in,
                              void* d_out, int out_size)
{
    const float* x = (const float*)d_in[0];
    const int n = in_sizes[0] / 10;                 // 1048576
    const int rpb = (n + GRID - 1) / GRID;          // 7085

    // two tiny direct memcpy nodes: GEMV weights -> cbank (LDCU/UR path)
    cudaMemcpyToSymbolAsync(cW1, d_in[1], 30 * sizeof(float), 0,
                            cudaMemcpyDeviceToDevice, 0);
    cudaMemcpyToSymbolAsync(cW2, d_in[9], 80 * sizeof(float), 0,
                            cudaMemcpyDeviceToDevice, 0);

    const size_t smem = (size_t)(6 * rpb + 512 + 8 + 8 + 4 + 21 + 3) * sizeof(float);
    cudaFuncSetAttribute(qfnn_kernel, cudaFuncAttributeMaxDynamicSharedMemorySize, (int)smem);
    qfnn_kernel<<<GRID, TPB, smem, 0>>>(
        x, (float*)d_out,
        (const float*)d_in[2], (const float*)d_in[3], (const float*)d_in[4],
        (const float*)d_in[5], (const float*)d_in[6], (const float*)d_in[7],
        (const float*)d_in[8], (const float*)d_in[10], n, rpb);
}